// round 12
// baseline (speedup 1.0000x reference)
#include <cuda_runtime.h>
#include <cuda_fp16.h>
#include <cstdint>

#define HW 128
#define CC 64
#define BBATCH 32
#define KK 1000
#define LL 12
#define OO 24

// h activations, NHWC fp32: [B][H][W][C] = 128 MB
__device__ float g_h[BBATCH * HW * HW * CC];

// ===================== small helpers =====================
__device__ __forceinline__ uint32_t smem_u32(const void* p) {
    uint32_t a;
    asm("{ .reg .u64 t; cvta.to.shared.u64 t, %1; cvt.u32.u64 %0, t; }" : "=r"(a) : "l"(p));
    return a;
}
__device__ __forceinline__ unsigned long long ffma2(unsigned long long a,
                                                    unsigned long long b,
                                                    unsigned long long c) {
    unsigned long long d;
    asm("fma.rn.f32x2 %0, %1, %2, %3;" : "=l"(d) : "l"(a), "l"(b), "l"(c));
    return d;
}
__device__ __forceinline__ unsigned long long addf2(unsigned long long a, unsigned long long b) {
    unsigned long long d;
    asm("add.rn.f32x2 %0, %1, %2;" : "=l"(d) : "l"(a), "l"(b));
    return d;
}
__device__ __forceinline__ unsigned long long pack2(float lo, float hi) {
    unsigned long long d;
    asm("mov.b64 %0, {%1, %2};" : "=l"(d) : "f"(lo), "f"(hi));
    return d;
}
__device__ __forceinline__ void unpack2(unsigned long long v, float& lo, float& hi) {
    asm("mov.b64 {%0, %1}, %2;" : "=f"(lo), "=f"(hi) : "l"(v));
}
__device__ __forceinline__ void ldsm4(uint32_t* r, uint32_t a) {
    asm volatile("ldmatrix.sync.aligned.m8n8.x4.shared.b16 {%0,%1,%2,%3}, [%4];"
                 : "=r"(r[0]), "=r"(r[1]), "=r"(r[2]), "=r"(r[3]) : "r"(a));
}
__device__ __forceinline__ void mma16816h(float* d, const uint32_t* a, uint32_t b0, uint32_t b1) {
    asm volatile("mma.sync.aligned.m16n8k16.row.col.f32.f16.f16.f32 "
                 "{%0,%1,%2,%3}, {%4,%5,%6,%7}, {%8,%9}, {%0,%1,%2,%3};"
                 : "+f"(d[0]), "+f"(d[1]), "+f"(d[2]), "+f"(d[3])
                 : "r"(a[0]), "r"(a[1]), "r"(a[2]), "r"(a[3]), "r"(b0), "r"(b1));
}
__device__ __forceinline__ uint32_t h2u(__half2 h) {
    return *reinterpret_cast<uint32_t*>(&h);
}

// ===================== conv smem layout (dynamic) =====================
#define ASTRIDE 144
#define ATILE (130 * 144)        // 18,720 B per input-row slab (fp16)
#define BTILE (64 * 144)         // 9,216 B per (dy,dx) tap tile
#define SM_B 0                   // 3 dx tiles for current dy: 27,648 B
#define SM_A 27648               // 4 slabs: 74,880 B -> ends 102,528
#define SM_BIAS 102528           // 64 floats
#define SM_TOT 102784

// ============================================================================
// Conv via mma.sync fp16 single-pass (unchanged — protected at ~231us).
// ============================================================================
__global__ __launch_bounds__(256) void conv_tc_kernel(
    const float* __restrict__ x,     // [B][C][H][W]
    const float* __restrict__ cw,    // [Cout][Cin][3][3]
    const float* __restrict__ bias)  // [C]
{
    extern __shared__ unsigned char smem[];
    const uint32_t sb = smem_u32(smem);
    const int t = threadIdx.x;
    const int lane = t & 31;
    const int w = t >> 5;
    const int y0 = blockIdx.x * 2;
    const int b = blockIdx.y;
    const int orow = w >> 2;
    const int pxl = (w & 3) * 32;

    if (t < 64) *reinterpret_cast<float*>(smem + SM_BIAS + t * 4) = bias[t];

    for (int i = t; i < 4 * 2 * 9; i += 256) {
        int slab = i / 18;
        int rem = i - slab * 18;
        int row = (rem >= 9) ? 129 : 0;
        int q = (rem >= 9) ? rem - 9 : rem;
        *reinterpret_cast<uint4*>(smem + SM_A + slab * ATILE + row * ASTRIDE + q * 16) =
            make_uint4(0, 0, 0, 0);
    }

    for (int i = t; i < 1024; i += 256) {
        int oct = i & 7;
        int pxq = (i >> 3) & 31;
        int r = i >> 8;
        int yin = y0 - 1 + r;
        uint32_t sbase = sb + SM_A + r * ATILE + (pxq * 4 + 1) * ASTRIDE + oct * 16;
        if ((unsigned)yin < 128u) {
            float4 v0, v1, v2, v3, v4, v5, v6, v7;
            const float* xp = x + ((size_t)(b * CC + oct * 8) * HW + yin) * HW + pxq * 4;
            const size_t cs = (size_t)HW * HW;
            v0 = *reinterpret_cast<const float4*>(xp);
            v1 = *reinterpret_cast<const float4*>(xp + cs);
            v2 = *reinterpret_cast<const float4*>(xp + 2 * cs);
            v3 = *reinterpret_cast<const float4*>(xp + 3 * cs);
            v4 = *reinterpret_cast<const float4*>(xp + 4 * cs);
            v5 = *reinterpret_cast<const float4*>(xp + 5 * cs);
            v6 = *reinterpret_cast<const float4*>(xp + 6 * cs);
            v7 = *reinterpret_cast<const float4*>(xp + 7 * cs);
#define STORE_PX(cmp, pi) do { \
            uint4 ov; \
            ov.x = h2u(__floats2half2_rn(v0.cmp, v1.cmp)); \
            ov.y = h2u(__floats2half2_rn(v2.cmp, v3.cmp)); \
            ov.z = h2u(__floats2half2_rn(v4.cmp, v5.cmp)); \
            ov.w = h2u(__floats2half2_rn(v6.cmp, v7.cmp)); \
            asm volatile("st.shared.v4.b32 [%0], {%1,%2,%3,%4};" \
                :: "r"(sbase + (pi) * ASTRIDE), "r"(ov.x), "r"(ov.y), "r"(ov.z), "r"(ov.w)); \
        } while (0)
            STORE_PX(x, 0);
            STORE_PX(y, 1);
            STORE_PX(z, 2);
            STORE_PX(w, 3);
#undef STORE_PX
        } else {
#pragma unroll
            for (int pi = 0; pi < 4; ++pi)
                asm volatile("st.shared.v4.b32 [%0], {%1,%1,%1,%1};"
                             :: "r"(sbase + pi * ASTRIDE), "r"(0u));
        }
    }

    const uint32_t aLaneOff = (uint32_t)((lane & 15) * ASTRIDE + (lane >> 4) * 16);
    const uint32_t bLaneOff = (uint32_t)((((lane & 7) + ((lane >> 4) << 3)) * ASTRIDE) +
                                         ((lane >> 3) & 1) * 16);

    float acc[2][8][4];
#pragma unroll
    for (int mt = 0; mt < 2; ++mt)
#pragma unroll
        for (int nt = 0; nt < 8; ++nt)
#pragma unroll
            for (int q = 0; q < 4; ++q) acc[mt][nt][q] = 0.f;

    for (int dy = 0; dy < 3; ++dy) {
        __syncthreads();
        for (int i = t; i < 4096; i += 256) {
            int co = i >> 6, ci = i & 63;
            const float* wp = cw + co * 576 + ci * 9 + dy * 3;
            unsigned char* basep = smem + SM_B + co * ASTRIDE + ci * 2;
            *reinterpret_cast<__half*>(basep) = __float2half(wp[0]);
            *reinterpret_cast<__half*>(basep + BTILE) = __float2half(wp[1]);
            *reinterpret_cast<__half*>(basep + 2 * BTILE) = __float2half(wp[2]);
        }
        __syncthreads();

        const uint32_t sA = sb + SM_A + (uint32_t)(orow + dy) * ATILE;

#pragma unroll
        for (int ks = 0; ks < 4; ++ks) {
#pragma unroll
            for (int dx = 0; dx < 3; ++dx) {
                uint32_t bf[4][4];
                const uint32_t bBase = sb + SM_B + (uint32_t)dx * BTILE + ks * 32 + bLaneOff;
#pragma unroll
                for (int np = 0; np < 4; ++np)
                    ldsm4(bf[np], bBase + np * 16 * ASTRIDE);
                uint32_t af[2][4];
#pragma unroll
                for (int mt = 0; mt < 2; ++mt) {
                    const uint32_t arow = (uint32_t)(pxl + mt * 16 + dx);
                    ldsm4(af[mt], sA + arow * ASTRIDE + ks * 32 + aLaneOff);
                }
#pragma unroll
                for (int mt = 0; mt < 2; ++mt)
#pragma unroll
                    for (int np = 0; np < 4; ++np) {
                        mma16816h(acc[mt][2 * np],     af[mt], bf[np][0], bf[np][1]);
                        mma16816h(acc[mt][2 * np + 1], af[mt], bf[np][2], bf[np][3]);
                    }
            }
        }
    }

    const float* sbias = reinterpret_cast<const float*>(smem + SM_BIAS);
    const int y = y0 + orow;
    const int cq = (lane & 3) * 2;
    const int pxq = lane >> 2;
#pragma unroll
    for (int mt = 0; mt < 2; ++mt) {
#pragma unroll
        for (int half = 0; half < 2; ++half) {
            int px = pxl + mt * 16 + pxq + half * 8;
            float* dst = g_h + (((size_t)(b * HW) + y) * HW + px) * CC;
#pragma unroll
            for (int nt = 0; nt < 8; ++nt) {
                int co = nt * 8 + cq;
                float a0 = acc[mt][nt][half * 2 + 0] + sbias[co];
                float a1 = acc[mt][nt][half * 2 + 1] + sbias[co + 1];
                a0 = a0 > 0.f ? a0 : 0.02f * a0;
                a1 = a1 > 0.f ? a1 : 0.02f * a1;
                *reinterpret_cast<float2*>(dst + co) = make_float2(a0, a1);
            }
        }
    }
}

// ============================================================================
// Gather + FC v6: block per (k, b-half); warp handles 2 b's -> ~110 regs
// -> 2 blocks/SM (occupancy 12.4% -> ~25%). pos staged in smem; depth-2
// prefetch retained.
// ============================================================================
__global__ __launch_bounds__(256) void gather_fc_kernel(
    const int* __restrict__ pos,     // [K][B][L][2] (x, y)
    const float* __restrict__ pw,    // [24][768]
    const float* __restrict__ pb,    // [24]
    float* __restrict__ out)         // [K][B][24]
{
    __shared__ float wsm[384 * 26];   // 39,936 B
    __shared__ int2 psm[16 * LL];     // 1,536 B (this half's 16 b's)

    const int t = threadIdx.x;
    const int lane = t & 31;
    const int w = t >> 5;
    const int k = blockIdx.x;
    const int bh = blockIdx.y;        // 0 or 1
    const int b0 = w * 2;             // local b within half (0..15)

    // stage this (k, half)'s positions (coalesced)
    {
        const int2* __restrict__ pos2 =
            reinterpret_cast<const int2*>(pos) + (k * BBATCH + bh * 16) * LL;
        for (int i = t; i < 16 * LL; i += 256) psm[i] = pos2[i];
    }

    unsigned long long acc[2][12];
#pragma unroll
    for (int bi = 0; bi < 2; ++bi)
#pragma unroll
        for (int op = 0; op < 12; ++op) acc[bi][op] = 0ULL;

    float hbuf[3][4];   // [slot][jj*2 + bi]

    for (int half = 0; half < 2; ++half) {
        __syncthreads();
        for (int i = t; i < 24 * 384; i += 256) {
            int o = i / 384;
            int jl = i - o * 384;
            wsm[jl * 26 + o] = pw[o * 768 + half * 384 + jl];
        }
        __syncthreads();   // also covers psm on first iteration

        // prefetch blocks 0 and 1
#pragma unroll
        for (int pp0 = 0; pp0 < 2; ++pp0) {
            const int l = half * 6 + pp0;
#pragma unroll
            for (int bi = 0; bi < 2; ++bi) {
                const int bl = b0 + bi;
                int2 pp = psm[bl * LL + l];
                int px = pp.x < 0 ? 0 : (pp.x > 127 ? 127 : pp.x);
                int py = pp.y < 0 ? 0 : (pp.y > 127 ? 127 : pp.y);
                const int bg = bh * 16 + bl;
                const float* hp = &g_h[(((size_t)(bg * HW) + py) * HW + px) * CC + lane];
                hbuf[pp0][bi]     = hp[0];
                hbuf[pp0][2 + bi] = hp[32];
            }
        }

#pragma unroll
        for (int p = 0; p < 6; ++p) {
            if (p < 4) {
                const int l = half * 6 + p + 2;
                const int slot = (p + 2) % 3;
#pragma unroll
                for (int bi = 0; bi < 2; ++bi) {
                    const int bl = b0 + bi;
                    int2 pp = psm[bl * LL + l];
                    int px = pp.x < 0 ? 0 : (pp.x > 127 ? 127 : pp.x);
                    int py = pp.y < 0 ? 0 : (pp.y > 127 ? 127 : pp.y);
                    const int bg = bh * 16 + bl;
                    const float* hp = &g_h[(((size_t)(bg * HW) + py) * HW + px) * CC + lane];
                    hbuf[slot][bi]     = hp[0];
                    hbuf[slot][2 + bi] = hp[32];
                }
            }
            const int slot = p % 3;
#pragma unroll
            for (int jj = 0; jj < 2; ++jj) {
                const int j24 = 2 * p + jj;
                const float2* wrow =
                    reinterpret_cast<const float2*>(&wsm[(j24 * 32 + lane) * 26]);
                float2 wv[12];
#pragma unroll
                for (int op = 0; op < 12; ++op) wv[op] = wrow[op];
#pragma unroll
                for (int bi = 0; bi < 2; ++bi) {
                    float hv = hbuf[slot][jj * 2 + bi];
                    unsigned long long hv2 = pack2(hv, hv);
#pragma unroll
                    for (int op = 0; op < 12; ++op)
                        acc[bi][op] = ffma2(pack2(wv[op].x, wv[op].y), hv2, acc[bi][op]);
                }
            }
        }
    }

    // butterfly reduce over lanes (packed f32x2 adds)
#pragma unroll
    for (int bi = 0; bi < 2; ++bi)
#pragma unroll
        for (int op = 0; op < 12; ++op) {
            unsigned long long v = acc[bi][op];
#pragma unroll
            for (int m = 16; m > 0; m >>= 1) {
                double o = __shfl_xor_sync(0xffffffffu, __longlong_as_double((long long)v), m);
                v = addf2(v, (unsigned long long)__double_as_longlong(o));
            }
            acc[bi][op] = v;
        }

#pragma unroll
    for (int bi = 0; bi < 2; ++bi) {
#pragma unroll
        for (int op = 0; op < 12; ++op) {
            if (lane == op) {
                float a0, a1;
                unpack2(acc[bi][op], a0, a1);
                float2 o2;
                o2.x = a0 + pb[2 * op];
                o2.y = a1 + pb[2 * op + 1];
                const int bg = bh * 16 + b0 + bi;
                *reinterpret_cast<float2*>(&out[(size_t)((k * BBATCH + bg) * OO) + 2 * op]) = o2;
            }
        }
    }
}

// ============================================================================
extern "C" void kernel_launch(void* const* d_in, const int* in_sizes, int n_in,
                              void* d_out, int out_size) {
    const float* x   = (const float*)d_in[0];   // [32][64][128][128]
    const int*   pos = (const int*)  d_in[1];   // [1000][32][12][2]
    const float* cw  = (const float*)d_in[2];   // [64][64][3][3]
    const float* cb  = (const float*)d_in[3];   // [64]
    const float* pw  = (const float*)d_in[4];   // [24][768]
    const float* pb  = (const float*)d_in[5];   // [24]
    float* out = (float*)d_out;                 // [1000][32][24]

    cudaFuncSetAttribute(conv_tc_kernel, cudaFuncAttributeMaxDynamicSharedMemorySize, SM_TOT);

    conv_tc_kernel<<<dim3(HW / 2, BBATCH), 256, SM_TOT>>>(x, cw, cb);
    gather_fc_kernel<<<dim3(KK, 2), 256>>>(pos, pw, pb, out);
}

// round 14
// speedup vs baseline: 1.0955x; 1.0955x over previous
#include <cuda_runtime.h>
#include <cuda_fp16.h>
#include <cstdint>

#define HW 128
#define CC 64
#define BBATCH 32
#define KK 1000
#define LL 12
#define OO 24

// h activations, NHWC fp32: [B][H][W][C] = 128 MB
__device__ float g_h[BBATCH * HW * HW * CC];

// ===================== small helpers =====================
__device__ __forceinline__ uint32_t smem_u32(const void* p) {
    uint32_t a;
    asm("{ .reg .u64 t; cvta.to.shared.u64 t, %1; cvt.u32.u64 %0, t; }" : "=r"(a) : "l"(p));
    return a;
}
__device__ __forceinline__ unsigned long long ffma2(unsigned long long a,
                                                    unsigned long long b,
                                                    unsigned long long c) {
    unsigned long long d;
    asm("fma.rn.f32x2 %0, %1, %2, %3;" : "=l"(d) : "l"(a), "l"(b), "l"(c));
    return d;
}
__device__ __forceinline__ unsigned long long addf2(unsigned long long a, unsigned long long b) {
    unsigned long long d;
    asm("add.rn.f32x2 %0, %1, %2;" : "=l"(d) : "l"(a), "l"(b));
    return d;
}
__device__ __forceinline__ unsigned long long pack2(float lo, float hi) {
    unsigned long long d;
    asm("mov.b64 %0, {%1, %2};" : "=l"(d) : "f"(lo), "f"(hi));
    return d;
}
__device__ __forceinline__ void unpack2(unsigned long long v, float& lo, float& hi) {
    asm("mov.b64 {%0, %1}, %2;" : "=f"(lo), "=f"(hi) : "l"(v));
}
__device__ __forceinline__ void ldsm4(uint32_t* r, uint32_t a) {
    asm volatile("ldmatrix.sync.aligned.m8n8.x4.shared.b16 {%0,%1,%2,%3}, [%4];"
                 : "=r"(r[0]), "=r"(r[1]), "=r"(r[2]), "=r"(r[3]) : "r"(a));
}
__device__ __forceinline__ void mma16816h(float* d, const uint32_t* a, uint32_t b0, uint32_t b1) {
    asm volatile("mma.sync.aligned.m16n8k16.row.col.f32.f16.f16.f32 "
                 "{%0,%1,%2,%3}, {%4,%5,%6,%7}, {%8,%9}, {%0,%1,%2,%3};"
                 : "+f"(d[0]), "+f"(d[1]), "+f"(d[2]), "+f"(d[3])
                 : "r"(a[0]), "r"(a[1]), "r"(a[2]), "r"(a[3]), "r"(b0), "r"(b1));
}
__device__ __forceinline__ uint32_t h2u(__half2 h) {
    return *reinterpret_cast<uint32_t*>(&h);
}

// ===================== conv smem layout (dynamic) =====================
#define ASTRIDE 144
#define ATILE (130 * 144)        // 18,720 B per input-row slab (fp16)
#define BTILE (64 * 144)         // 9,216 B per (dy,dx) tap tile
#define SM_B 0                   // 3 dx tiles for current dy: 27,648 B
#define SM_A 27648               // 4 slabs: 74,880 B -> ends 102,528
#define SM_BIAS 102528           // 64 floats
#define SM_TOT 102784

// ============================================================================
// Conv via mma.sync fp16 single-pass (unchanged — protected at ~231us).
// ============================================================================
__global__ __launch_bounds__(256) void conv_tc_kernel(
    const float* __restrict__ x,     // [B][C][H][W]
    const float* __restrict__ cw,    // [Cout][Cin][3][3]
    const float* __restrict__ bias)  // [C]
{
    extern __shared__ unsigned char smem[];
    const uint32_t sb = smem_u32(smem);
    const int t = threadIdx.x;
    const int lane = t & 31;
    const int w = t >> 5;
    const int y0 = blockIdx.x * 2;
    const int b = blockIdx.y;
    const int orow = w >> 2;
    const int pxl = (w & 3) * 32;

    if (t < 64) *reinterpret_cast<float*>(smem + SM_BIAS + t * 4) = bias[t];

    for (int i = t; i < 4 * 2 * 9; i += 256) {
        int slab = i / 18;
        int rem = i - slab * 18;
        int row = (rem >= 9) ? 129 : 0;
        int q = (rem >= 9) ? rem - 9 : rem;
        *reinterpret_cast<uint4*>(smem + SM_A + slab * ATILE + row * ASTRIDE + q * 16) =
            make_uint4(0, 0, 0, 0);
    }

    for (int i = t; i < 1024; i += 256) {
        int oct = i & 7;
        int pxq = (i >> 3) & 31;
        int r = i >> 8;
        int yin = y0 - 1 + r;
        uint32_t sbase = sb + SM_A + r * ATILE + (pxq * 4 + 1) * ASTRIDE + oct * 16;
        if ((unsigned)yin < 128u) {
            float4 v0, v1, v2, v3, v4, v5, v6, v7;
            const float* xp = x + ((size_t)(b * CC + oct * 8) * HW + yin) * HW + pxq * 4;
            const size_t cs = (size_t)HW * HW;
            v0 = *reinterpret_cast<const float4*>(xp);
            v1 = *reinterpret_cast<const float4*>(xp + cs);
            v2 = *reinterpret_cast<const float4*>(xp + 2 * cs);
            v3 = *reinterpret_cast<const float4*>(xp + 3 * cs);
            v4 = *reinterpret_cast<const float4*>(xp + 4 * cs);
            v5 = *reinterpret_cast<const float4*>(xp + 5 * cs);
            v6 = *reinterpret_cast<const float4*>(xp + 6 * cs);
            v7 = *reinterpret_cast<const float4*>(xp + 7 * cs);
#define STORE_PX(cmp, pi) do { \
            uint4 ov; \
            ov.x = h2u(__floats2half2_rn(v0.cmp, v1.cmp)); \
            ov.y = h2u(__floats2half2_rn(v2.cmp, v3.cmp)); \
            ov.z = h2u(__floats2half2_rn(v4.cmp, v5.cmp)); \
            ov.w = h2u(__floats2half2_rn(v6.cmp, v7.cmp)); \
            asm volatile("st.shared.v4.b32 [%0], {%1,%2,%3,%4};" \
                :: "r"(sbase + (pi) * ASTRIDE), "r"(ov.x), "r"(ov.y), "r"(ov.z), "r"(ov.w)); \
        } while (0)
            STORE_PX(x, 0);
            STORE_PX(y, 1);
            STORE_PX(z, 2);
            STORE_PX(w, 3);
#undef STORE_PX
        } else {
#pragma unroll
            for (int pi = 0; pi < 4; ++pi)
                asm volatile("st.shared.v4.b32 [%0], {%1,%1,%1,%1};"
                             :: "r"(sbase + pi * ASTRIDE), "r"(0u));
        }
    }

    const uint32_t aLaneOff = (uint32_t)((lane & 15) * ASTRIDE + (lane >> 4) * 16);
    const uint32_t bLaneOff = (uint32_t)((((lane & 7) + ((lane >> 4) << 3)) * ASTRIDE) +
                                         ((lane >> 3) & 1) * 16);

    float acc[2][8][4];
#pragma unroll
    for (int mt = 0; mt < 2; ++mt)
#pragma unroll
        for (int nt = 0; nt < 8; ++nt)
#pragma unroll
            for (int q = 0; q < 4; ++q) acc[mt][nt][q] = 0.f;

    for (int dy = 0; dy < 3; ++dy) {
        __syncthreads();
        for (int i = t; i < 4096; i += 256) {
            int co = i >> 6, ci = i & 63;
            const float* wp = cw + co * 576 + ci * 9 + dy * 3;
            unsigned char* basep = smem + SM_B + co * ASTRIDE + ci * 2;
            *reinterpret_cast<__half*>(basep) = __float2half(wp[0]);
            *reinterpret_cast<__half*>(basep + BTILE) = __float2half(wp[1]);
            *reinterpret_cast<__half*>(basep + 2 * BTILE) = __float2half(wp[2]);
        }
        __syncthreads();

        const uint32_t sA = sb + SM_A + (uint32_t)(orow + dy) * ATILE;

#pragma unroll
        for (int ks = 0; ks < 4; ++ks) {
#pragma unroll
            for (int dx = 0; dx < 3; ++dx) {
                uint32_t bf[4][4];
                const uint32_t bBase = sb + SM_B + (uint32_t)dx * BTILE + ks * 32 + bLaneOff;
#pragma unroll
                for (int np = 0; np < 4; ++np)
                    ldsm4(bf[np], bBase + np * 16 * ASTRIDE);
                uint32_t af[2][4];
#pragma unroll
                for (int mt = 0; mt < 2; ++mt) {
                    const uint32_t arow = (uint32_t)(pxl + mt * 16 + dx);
                    ldsm4(af[mt], sA + arow * ASTRIDE + ks * 32 + aLaneOff);
                }
#pragma unroll
                for (int mt = 0; mt < 2; ++mt)
#pragma unroll
                    for (int np = 0; np < 4; ++np) {
                        mma16816h(acc[mt][2 * np],     af[mt], bf[np][0], bf[np][1]);
                        mma16816h(acc[mt][2 * np + 1], af[mt], bf[np][2], bf[np][3]);
                    }
            }
        }
    }

    const float* sbias = reinterpret_cast<const float*>(smem + SM_BIAS);
    const int y = y0 + orow;
    const int cq = (lane & 3) * 2;
    const int pxq = lane >> 2;
#pragma unroll
    for (int mt = 0; mt < 2; ++mt) {
#pragma unroll
        for (int half = 0; half < 2; ++half) {
            int px = pxl + mt * 16 + pxq + half * 8;
            float* dst = g_h + (((size_t)(b * HW) + y) * HW + px) * CC;
#pragma unroll
            for (int nt = 0; nt < 8; ++nt) {
                int co = nt * 8 + cq;
                float a0 = acc[mt][nt][half * 2 + 0] + sbias[co];
                float a1 = acc[mt][nt][half * 2 + 1] + sbias[co + 1];
                a0 = a0 > 0.f ? a0 : 0.02f * a0;
                a1 = a1 > 0.f ? a1 : 0.02f * a1;
                *reinterpret_cast<float2*>(dst + co) = make_float2(a0, a1);
            }
        }
    }
}

// ============================================================================
// Gather + FC v7: block per (k, b-half); warp handles 2 b's; 2 blocks/SM.
// Weight operands loaded as pre-packed 8B (LDS.64 -> FFMA2 operand, no MOV
// packing) and hoisted once per j24 across both b's. Vectorized staging.
// ============================================================================
__global__ __launch_bounds__(256, 2) void gather_fc_kernel(
    const int* __restrict__ pos,     // [K][B][L][2] (x, y)
    const float* __restrict__ pw,    // [24][768]
    const float* __restrict__ pb,    // [24]
    float* __restrict__ out)         // [K][B][24]
{
    __shared__ float wsm[384 * 26];   // 39,936 B
    __shared__ int2 psm[16 * LL];     // 1,536 B

    const int t = threadIdx.x;
    const int lane = t & 31;
    const int w = t >> 5;
    const int k = blockIdx.x;
    const int bh = blockIdx.y;        // 0 or 1
    const int b0 = w * 2;             // local b within half (0..15)

    // stage this (k, half)'s positions (coalesced)
    {
        const int2* __restrict__ pos2 =
            reinterpret_cast<const int2*>(pos) + (k * BBATCH + bh * 16) * LL;
        for (int i = t; i < 16 * LL; i += 256) psm[i] = pos2[i];
    }

    unsigned long long acc[2][12];
#pragma unroll
    for (int bi = 0; bi < 2; ++bi)
#pragma unroll
        for (int op = 0; op < 12; ++op) acc[bi][op] = 0ULL;

    float hbuf[3][4];   // [slot][jj*2 + bi]

    for (int half = 0; half < 2; ++half) {
        __syncthreads();
        // vectorized weight staging: float4 loads, 4 scalar STS (transposed)
        for (int i = t * 4; i < 24 * 384; i += 1024) {
            int o = i / 384;
            int jl = i - o * 384;
            float4 v = *reinterpret_cast<const float4*>(&pw[o * 768 + half * 384 + jl]);
            wsm[(jl + 0) * 26 + o] = v.x;
            wsm[(jl + 1) * 26 + o] = v.y;
            wsm[(jl + 2) * 26 + o] = v.z;
            wsm[(jl + 3) * 26 + o] = v.w;
        }
        __syncthreads();   // also covers psm on first iteration

        // prefetch blocks 0 and 1
#pragma unroll
        for (int pp0 = 0; pp0 < 2; ++pp0) {
            const int l = half * 6 + pp0;
#pragma unroll
            for (int bi = 0; bi < 2; ++bi) {
                const int bl = b0 + bi;
                int2 pp = psm[bl * LL + l];
                int px = pp.x < 0 ? 0 : (pp.x > 127 ? 127 : pp.x);
                int py = pp.y < 0 ? 0 : (pp.y > 127 ? 127 : pp.y);
                const int bg = bh * 16 + bl;
                const float* hp = &g_h[(((size_t)(bg * HW) + py) * HW + px) * CC + lane];
                hbuf[pp0][bi]     = hp[0];
                hbuf[pp0][2 + bi] = hp[32];
            }
        }

#pragma unroll
        for (int p = 0; p < 6; ++p) {
            if (p < 4) {
                const int l = half * 6 + p + 2;
                const int slot = (p + 2) % 3;
#pragma unroll
                for (int bi = 0; bi < 2; ++bi) {
                    const int bl = b0 + bi;
                    int2 pp = psm[bl * LL + l];
                    int px = pp.x < 0 ? 0 : (pp.x > 127 ? 127 : pp.x);
                    int py = pp.y < 0 ? 0 : (pp.y > 127 ? 127 : pp.y);
                    const int bg = bh * 16 + bl;
                    const float* hp = &g_h[(((size_t)(bg * HW) + py) * HW + px) * CC + lane];
                    hbuf[slot][bi]     = hp[0];
                    hbuf[slot][2 + bi] = hp[32];
                }
            }
            const int slot = p % 3;
#pragma unroll
            for (int jj = 0; jj < 2; ++jj) {
                const int j24 = 2 * p + jj;
                // weight operands: 12 x LDS.64, directly FFMA2-consumable,
                // shared across both b's (no per-op packing MOVs)
                const unsigned long long* wrow =
                    reinterpret_cast<const unsigned long long*>(&wsm[(j24 * 32 + lane) * 26]);
                unsigned long long wvp[12];
#pragma unroll
                for (int op = 0; op < 12; ++op) wvp[op] = wrow[op];
#pragma unroll
                for (int bi = 0; bi < 2; ++bi) {
                    float hv = hbuf[slot][jj * 2 + bi];
                    unsigned long long hv2 = pack2(hv, hv);
#pragma unroll
                    for (int op = 0; op < 12; ++op)
                        acc[bi][op] = ffma2(wvp[op], hv2, acc[bi][op]);
                }
            }
        }
    }

    // butterfly reduce over lanes (packed f32x2 adds)
#pragma unroll
    for (int bi = 0; bi < 2; ++bi)
#pragma unroll
        for (int op = 0; op < 12; ++op) {
            unsigned long long v = acc[bi][op];
#pragma unroll
            for (int m = 16; m > 0; m >>= 1) {
                double o = __shfl_xor_sync(0xffffffffu, __longlong_as_double((long long)v), m);
                v = addf2(v, (unsigned long long)__double_as_longlong(o));
            }
            acc[bi][op] = v;
        }

#pragma unroll
    for (int bi = 0; bi < 2; ++bi) {
#pragma unroll
        for (int op = 0; op < 12; ++op) {
            if (lane == op) {
                float a0, a1;
                unpack2(acc[bi][op], a0, a1);
                float2 o2;
                o2.x = a0 + pb[2 * op];
                o2.y = a1 + pb[2 * op + 1];
                const int bg = bh * 16 + b0 + bi;
                *reinterpret_cast<float2*>(&out[(size_t)((k * BBATCH + bg) * OO) + 2 * op]) = o2;
            }
        }
    }
}

// ============================================================================
extern "C" void kernel_launch(void* const* d_in, const int* in_sizes, int n_in,
                              void* d_out, int out_size) {
    const float* x   = (const float*)d_in[0];   // [32][64][128][128]
    const int*   pos = (const int*)  d_in[1];   // [1000][32][12][2]
    const float* cw  = (const float*)d_in[2];   // [64][64][3][3]
    const float* cb  = (const float*)d_in[3];   // [64]
    const float* pw  = (const float*)d_in[4];   // [24][768]
    const float* pb  = (const float*)d_in[5];   // [24]
    float* out = (float*)d_out;                 // [1000][32][24]

    cudaFuncSetAttribute(conv_tc_kernel, cudaFuncAttributeMaxDynamicSharedMemorySize, SM_TOT);

    conv_tc_kernel<<<dim3(HW / 2, BBATCH), 256, SM_TOT>>>(x, cw, cb);
    gather_fc_kernel<<<dim3(KK, 2), 256>>>(pos, pw, pb, out);
}

// round 16
// speedup vs baseline: 1.1501x; 1.0498x over previous
#include <cuda_runtime.h>
#include <cuda_fp16.h>
#include <cstdint>

#define HW 128
#define CC 64
#define BBATCH 32
#define KK 1000
#define LL 12
#define OO 24

// h activations, NHWC fp32: [B][H][W][C] = 128 MB
__device__ float g_h[BBATCH * HW * HW * CC];

// ===================== small helpers =====================
__device__ __forceinline__ uint32_t smem_u32(const void* p) {
    uint32_t a;
    asm("{ .reg .u64 t; cvta.to.shared.u64 t, %1; cvt.u32.u64 %0, t; }" : "=r"(a) : "l"(p));
    return a;
}
__device__ __forceinline__ unsigned long long ffma2(unsigned long long a,
                                                    unsigned long long b,
                                                    unsigned long long c) {
    unsigned long long d;
    asm("fma.rn.f32x2 %0, %1, %2, %3;" : "=l"(d) : "l"(a), "l"(b), "l"(c));
    return d;
}
__device__ __forceinline__ unsigned long long addf2(unsigned long long a, unsigned long long b) {
    unsigned long long d;
    asm("add.rn.f32x2 %0, %1, %2;" : "=l"(d) : "l"(a), "l"(b));
    return d;
}
__device__ __forceinline__ unsigned long long pack2(float lo, float hi) {
    unsigned long long d;
    asm("mov.b64 %0, {%1, %2};" : "=l"(d) : "f"(lo), "f"(hi));
    return d;
}
__device__ __forceinline__ void unpack2(unsigned long long v, float& lo, float& hi) {
    asm("mov.b64 {%0, %1}, %2;" : "=f"(lo), "=f"(hi) : "l"(v));
}
__device__ __forceinline__ void ldsm4(uint32_t* r, uint32_t a) {
    asm volatile("ldmatrix.sync.aligned.m8n8.x4.shared.b16 {%0,%1,%2,%3}, [%4];"
                 : "=r"(r[0]), "=r"(r[1]), "=r"(r[2]), "=r"(r[3]) : "r"(a));
}
__device__ __forceinline__ void mma16816h(float* d, const uint32_t* a, uint32_t b0, uint32_t b1) {
    asm volatile("mma.sync.aligned.m16n8k16.row.col.f32.f16.f16.f32 "
                 "{%0,%1,%2,%3}, {%4,%5,%6,%7}, {%8,%9}, {%0,%1,%2,%3};"
                 : "+f"(d[0]), "+f"(d[1]), "+f"(d[2]), "+f"(d[3])
                 : "r"(a[0]), "r"(a[1]), "r"(a[2]), "r"(a[3]), "r"(b0), "r"(b1));
}
__device__ __forceinline__ uint32_t h2u(__half2 h) {
    return *reinterpret_cast<uint32_t*>(&h);
}

// ===================== conv smem layout (dynamic) =====================
#define ASTRIDE 144
#define ATILE (130 * 144)        // 18,720 B per input-row slab (fp16)
#define BTILE (64 * 144)         // 9,216 B per (dy,dx) tap tile
#define SM_B 0                   // 3 dx tiles for current dy: 27,648 B
#define SM_A 27648               // 4 slabs: 74,880 B -> ends 102,528
#define SM_BIAS 102528           // 64 floats
#define SM_TOT 102784

// ===================== gather smem layout (dynamic) =====================
#define GW_STRIDE 26
#define G_WSM_BYTES (768 * GW_STRIDE * 4)   // 79,872
#define G_PSM_OFF   G_WSM_BYTES
#define G_TOT       (G_WSM_BYTES + 16 * LL * 8)   // 81,408
#define KPB 8                                // k's per block

// ============================================================================
// Conv via mma.sync fp16 single-pass (unchanged — protected at ~230us).
// ============================================================================
__global__ __launch_bounds__(256) void conv_tc_kernel(
    const float* __restrict__ x,     // [B][C][H][W]
    const float* __restrict__ cw,    // [Cout][Cin][3][3]
    const float* __restrict__ bias)  // [C]
{
    extern __shared__ unsigned char smem[];
    const uint32_t sb = smem_u32(smem);
    const int t = threadIdx.x;
    const int lane = t & 31;
    const int w = t >> 5;
    const int y0 = blockIdx.x * 2;
    const int b = blockIdx.y;
    const int orow = w >> 2;
    const int pxl = (w & 3) * 32;

    if (t < 64) *reinterpret_cast<float*>(smem + SM_BIAS + t * 4) = bias[t];

    for (int i = t; i < 4 * 2 * 9; i += 256) {
        int slab = i / 18;
        int rem = i - slab * 18;
        int row = (rem >= 9) ? 129 : 0;
        int q = (rem >= 9) ? rem - 9 : rem;
        *reinterpret_cast<uint4*>(smem + SM_A + slab * ATILE + row * ASTRIDE + q * 16) =
            make_uint4(0, 0, 0, 0);
    }

    for (int i = t; i < 1024; i += 256) {
        int oct = i & 7;
        int pxq = (i >> 3) & 31;
        int r = i >> 8;
        int yin = y0 - 1 + r;
        uint32_t sbase = sb + SM_A + r * ATILE + (pxq * 4 + 1) * ASTRIDE + oct * 16;
        if ((unsigned)yin < 128u) {
            float4 v0, v1, v2, v3, v4, v5, v6, v7;
            const float* xp = x + ((size_t)(b * CC + oct * 8) * HW + yin) * HW + pxq * 4;
            const size_t cs = (size_t)HW * HW;
            v0 = *reinterpret_cast<const float4*>(xp);
            v1 = *reinterpret_cast<const float4*>(xp + cs);
            v2 = *reinterpret_cast<const float4*>(xp + 2 * cs);
            v3 = *reinterpret_cast<const float4*>(xp + 3 * cs);
            v4 = *reinterpret_cast<const float4*>(xp + 4 * cs);
            v5 = *reinterpret_cast<const float4*>(xp + 5 * cs);
            v6 = *reinterpret_cast<const float4*>(xp + 6 * cs);
            v7 = *reinterpret_cast<const float4*>(xp + 7 * cs);
#define STORE_PX(cmp, pi) do { \
            uint4 ov; \
            ov.x = h2u(__floats2half2_rn(v0.cmp, v1.cmp)); \
            ov.y = h2u(__floats2half2_rn(v2.cmp, v3.cmp)); \
            ov.z = h2u(__floats2half2_rn(v4.cmp, v5.cmp)); \
            ov.w = h2u(__floats2half2_rn(v6.cmp, v7.cmp)); \
            asm volatile("st.shared.v4.b32 [%0], {%1,%2,%3,%4};" \
                :: "r"(sbase + (pi) * ASTRIDE), "r"(ov.x), "r"(ov.y), "r"(ov.z), "r"(ov.w)); \
        } while (0)
            STORE_PX(x, 0);
            STORE_PX(y, 1);
            STORE_PX(z, 2);
            STORE_PX(w, 3);
#undef STORE_PX
        } else {
#pragma unroll
            for (int pi = 0; pi < 4; ++pi)
                asm volatile("st.shared.v4.b32 [%0], {%1,%1,%1,%1};"
                             :: "r"(sbase + pi * ASTRIDE), "r"(0u));
        }
    }

    const uint32_t aLaneOff = (uint32_t)((lane & 15) * ASTRIDE + (lane >> 4) * 16);
    const uint32_t bLaneOff = (uint32_t)((((lane & 7) + ((lane >> 4) << 3)) * ASTRIDE) +
                                         ((lane >> 3) & 1) * 16);

    float acc[2][8][4];
#pragma unroll
    for (int mt = 0; mt < 2; ++mt)
#pragma unroll
        for (int nt = 0; nt < 8; ++nt)
#pragma unroll
            for (int q = 0; q < 4; ++q) acc[mt][nt][q] = 0.f;

    for (int dy = 0; dy < 3; ++dy) {
        __syncthreads();
        for (int i = t; i < 4096; i += 256) {
            int co = i >> 6, ci = i & 63;
            const float* wp = cw + co * 576 + ci * 9 + dy * 3;
            unsigned char* basep = smem + SM_B + co * ASTRIDE + ci * 2;
            *reinterpret_cast<__half*>(basep) = __float2half(wp[0]);
            *reinterpret_cast<__half*>(basep + BTILE) = __float2half(wp[1]);
            *reinterpret_cast<__half*>(basep + 2 * BTILE) = __float2half(wp[2]);
        }
        __syncthreads();

        const uint32_t sA = sb + SM_A + (uint32_t)(orow + dy) * ATILE;

#pragma unroll
        for (int ks = 0; ks < 4; ++ks) {
#pragma unroll
            for (int dx = 0; dx < 3; ++dx) {
                uint32_t bf[4][4];
                const uint32_t bBase = sb + SM_B + (uint32_t)dx * BTILE + ks * 32 + bLaneOff;
#pragma unroll
                for (int np = 0; np < 4; ++np)
                    ldsm4(bf[np], bBase + np * 16 * ASTRIDE);
                uint32_t af[2][4];
#pragma unroll
                for (int mt = 0; mt < 2; ++mt) {
                    const uint32_t arow = (uint32_t)(pxl + mt * 16 + dx);
                    ldsm4(af[mt], sA + arow * ASTRIDE + ks * 32 + aLaneOff);
                }
#pragma unroll
                for (int mt = 0; mt < 2; ++mt)
#pragma unroll
                    for (int np = 0; np < 4; ++np) {
                        mma16816h(acc[mt][2 * np],     af[mt], bf[np][0], bf[np][1]);
                        mma16816h(acc[mt][2 * np + 1], af[mt], bf[np][2], bf[np][3]);
                    }
            }
        }
    }

    const float* sbias = reinterpret_cast<const float*>(smem + SM_BIAS);
    const int y = y0 + orow;
    const int cq = (lane & 3) * 2;
    const int pxq = lane >> 2;
#pragma unroll
    for (int mt = 0; mt < 2; ++mt) {
#pragma unroll
        for (int half = 0; half < 2; ++half) {
            int px = pxl + mt * 16 + pxq + half * 8;
            float* dst = g_h + (((size_t)(b * HW) + y) * HW + px) * CC;
#pragma unroll
            for (int nt = 0; nt < 8; ++nt) {
                int co = nt * 8 + cq;
                float a0 = acc[mt][nt][half * 2 + 0] + sbias[co];
                float a1 = acc[mt][nt][half * 2 + 1] + sbias[co + 1];
                a0 = a0 > 0.f ? a0 : 0.02f * a0;
                a1 = a1 > 0.f ? a1 : 0.02f * a1;
                *reinterpret_cast<float2*>(dst + co) = make_float2(a0, a1);
            }
        }
    }
}

// ============================================================================
// Gather + FC v8: block per (8 k's, b-half); full pred_w staged ONCE per
// block in dynamic smem (79.9 KB) -> staging cost and pw L2 traffic /16.
// Warp handles 2 b's; LDS.64 pre-packed weight operands; depth-2 prefetch.
// ============================================================================
__global__ __launch_bounds__(256, 2) void gather_fc_kernel(
    const int* __restrict__ pos,     // [K][B][L][2] (x, y)
    const float* __restrict__ pw,    // [24][768]
    const float* __restrict__ pb,    // [24]
    float* __restrict__ out)         // [K][B][24]
{
    extern __shared__ unsigned char gsm[];
    float* wsm = reinterpret_cast<float*>(gsm);                 // [768][26]
    int2* psm = reinterpret_cast<int2*>(gsm + G_PSM_OFF);       // [16][12]

    const int t = threadIdx.x;
    const int lane = t & 31;
    const int w = t >> 5;
    const int k0 = blockIdx.x * KPB;
    const int bh = blockIdx.y;        // 0 or 1
    const int b0 = w * 2;             // local b within half (0..15)

    // stage FULL pred_w once: wsm[j*26 + o], j in [0,768)
    for (int i = t * 4; i < 24 * 768; i += 1024) {
        int o = i / 768;
        int jl = i - o * 768;
        float4 v = *reinterpret_cast<const float4*>(&pw[o * 768 + jl]);
        wsm[(jl + 0) * GW_STRIDE + o] = v.x;
        wsm[(jl + 1) * GW_STRIDE + o] = v.y;
        wsm[(jl + 2) * GW_STRIDE + o] = v.z;
        wsm[(jl + 3) * GW_STRIDE + o] = v.w;
    }

    for (int kk = 0; kk < KPB; ++kk) {
        const int k = k0 + kk;
        __syncthreads();   // wsm ready (first iter) / psm readers done (later)
        {
            const int2* __restrict__ pos2 =
                reinterpret_cast<const int2*>(pos) + (k * BBATCH + bh * 16) * LL;
            for (int i = t; i < 16 * LL; i += 256) psm[i] = pos2[i];
        }
        __syncthreads();

        unsigned long long acc[2][12];
#pragma unroll
        for (int bi = 0; bi < 2; ++bi)
#pragma unroll
            for (int op = 0; op < 12; ++op) acc[bi][op] = 0ULL;

        float hbuf[3][4];   // [slot][jj*2 + bi]

        // prefetch l = 0, 1
#pragma unroll
        for (int pp0 = 0; pp0 < 2; ++pp0) {
#pragma unroll
            for (int bi = 0; bi < 2; ++bi) {
                const int bl = b0 + bi;
                int2 pp = psm[bl * LL + pp0];
                int px = pp.x < 0 ? 0 : (pp.x > 127 ? 127 : pp.x);
                int py = pp.y < 0 ? 0 : (pp.y > 127 ? 127 : pp.y);
                const int bg = bh * 16 + bl;
                const float* hp = &g_h[(((size_t)(bg * HW) + py) * HW + px) * CC + lane];
                hbuf[pp0][bi]     = hp[0];
                hbuf[pp0][2 + bi] = hp[32];
            }
        }

#pragma unroll
        for (int l = 0; l < 12; ++l) {
            if (l < 10) {
                const int slot = (l + 2) % 3;
#pragma unroll
                for (int bi = 0; bi < 2; ++bi) {
                    const int bl = b0 + bi;
                    int2 pp = psm[bl * LL + l + 2];
                    int px = pp.x < 0 ? 0 : (pp.x > 127 ? 127 : pp.x);
                    int py = pp.y < 0 ? 0 : (pp.y > 127 ? 127 : pp.y);
                    const int bg = bh * 16 + bl;
                    const float* hp = &g_h[(((size_t)(bg * HW) + py) * HW + px) * CC + lane];
                    hbuf[slot][bi]     = hp[0];
                    hbuf[slot][2 + bi] = hp[32];
                }
            }
            const int slot = l % 3;
#pragma unroll
            for (int jj = 0; jj < 2; ++jj) {
                const int jrow = (l * 2 + jj) * 32 + lane;   // j in [0,768)
                const unsigned long long* wrow =
                    reinterpret_cast<const unsigned long long*>(&wsm[jrow * GW_STRIDE]);
                unsigned long long wvp[12];
#pragma unroll
                for (int op = 0; op < 12; ++op) wvp[op] = wrow[op];
#pragma unroll
                for (int bi = 0; bi < 2; ++bi) {
                    float hv = hbuf[slot][jj * 2 + bi];
                    unsigned long long hv2 = pack2(hv, hv);
#pragma unroll
                    for (int op = 0; op < 12; ++op)
                        acc[bi][op] = ffma2(wvp[op], hv2, acc[bi][op]);
                }
            }
        }

        // butterfly reduce + write for this k
#pragma unroll
        for (int bi = 0; bi < 2; ++bi)
#pragma unroll
            for (int op = 0; op < 12; ++op) {
                unsigned long long v = acc[bi][op];
#pragma unroll
                for (int m = 16; m > 0; m >>= 1) {
                    double o = __shfl_xor_sync(0xffffffffu, __longlong_as_double((long long)v), m);
                    v = addf2(v, (unsigned long long)__double_as_longlong(o));
                }
                acc[bi][op] = v;
            }

#pragma unroll
        for (int bi = 0; bi < 2; ++bi) {
#pragma unroll
            for (int op = 0; op < 12; ++op) {
                if (lane == op) {
                    float a0, a1;
                    unpack2(acc[bi][op], a0, a1);
                    float2 o2;
                    o2.x = a0 + pb[2 * op];
                    o2.y = a1 + pb[2 * op + 1];
                    const int bg = bh * 16 + b0 + bi;
                    *reinterpret_cast<float2*>(&out[(size_t)((k * BBATCH + bg) * OO) + 2 * op]) = o2;
                }
            }
        }
    }
}

// ============================================================================
extern "C" void kernel_launch(void* const* d_in, const int* in_sizes, int n_in,
                              void* d_out, int out_size) {
    const float* x   = (const float*)d_in[0];   // [32][64][128][128]
    const int*   pos = (const int*)  d_in[1];   // [1000][32][12][2]
    const float* cw  = (const float*)d_in[2];   // [64][64][3][3]
    const float* cb  = (const float*)d_in[3];   // [64]
    const float* pw  = (const float*)d_in[4];   // [24][768]
    const float* pb  = (const float*)d_in[5];   // [24]
    float* out = (float*)d_out;                 // [1000][32][24]

    cudaFuncSetAttribute(conv_tc_kernel, cudaFuncAttributeMaxDynamicSharedMemorySize, SM_TOT);
    cudaFuncSetAttribute(gather_fc_kernel, cudaFuncAttributeMaxDynamicSharedMemorySize, G_TOT);

    conv_tc_kernel<<<dim3(HW / 2, BBATCH), 256, SM_TOT>>>(x, cw, cb);
    gather_fc_kernel<<<dim3(KK / KPB, 2), 256, G_TOT>>>(pos, pw, pb, out);
}

// round 17
// speedup vs baseline: 1.3047x; 1.1345x over previous
#include <cuda_runtime.h>
#include <cuda_fp16.h>
#include <cstdint>

#define HW 128
#define CC 64
#define BBATCH 32
#define KK 1000
#define LL 12
#define OO 24

// h activations, NHWC fp32: [B][H][W][C] = 128 MB
__device__ float g_h[BBATCH * HW * HW * CC];

// ===================== small helpers =====================
__device__ __forceinline__ uint32_t smem_u32(const void* p) {
    uint32_t a;
    asm("{ .reg .u64 t; cvta.to.shared.u64 t, %1; cvt.u32.u64 %0, t; }" : "=r"(a) : "l"(p));
    return a;
}
__device__ __forceinline__ void ldsm4(uint32_t* r, uint32_t a) {
    asm volatile("ldmatrix.sync.aligned.m8n8.x4.shared.b16 {%0,%1,%2,%3}, [%4];"
                 : "=r"(r[0]), "=r"(r[1]), "=r"(r[2]), "=r"(r[3]) : "r"(a));
}
__device__ __forceinline__ void ldsm2(uint32_t* r, uint32_t a) {
    asm volatile("ldmatrix.sync.aligned.m8n8.x2.shared.b16 {%0,%1}, [%2];"
                 : "=r"(r[0]), "=r"(r[1]) : "r"(a));
}
__device__ __forceinline__ void mma16816h(float* d, const uint32_t* a, uint32_t b0, uint32_t b1) {
    asm volatile("mma.sync.aligned.m16n8k16.row.col.f32.f16.f16.f32 "
                 "{%0,%1,%2,%3}, {%4,%5,%6,%7}, {%8,%9}, {%0,%1,%2,%3};"
                 : "+f"(d[0]), "+f"(d[1]), "+f"(d[2]), "+f"(d[3])
                 : "r"(a[0]), "r"(a[1]), "r"(a[2]), "r"(a[3]), "r"(b0), "r"(b1));
}
__device__ __forceinline__ uint32_t h2u(__half2 h) {
    return *reinterpret_cast<uint32_t*>(&h);
}

// ===================== conv smem layout (dynamic) =====================
#define ASTRIDE 144
#define ATILE (130 * 144)        // 18,720 B per input-row slab (fp16)
#define BTILE (64 * 144)         // 9,216 B per (dy,dx) tap tile
#define SM_B 0                   // 3 dx tiles for current dy: 27,648 B
#define SM_A 27648               // 4 slabs: 74,880 B -> ends 102,528
#define SM_BIAS 102528           // 64 floats
#define SM_TOT 102784

// ===================== gather-mma smem layout (dynamic) =====================
#define GSTRIDE_B 1552           // 776 halves per row (768 + 8 pad)
#define SM_GA 0                  // A: 32 rows x 1552 B = 49,664
#define SM_GB 49664              // B: 24 rows x 1552 B = 37,248
#define G_TOT (49664 + 37248)    // 86,912

// ============================================================================
// Conv via mma.sync fp16 single-pass (unchanged — protected at ~230us).
// ============================================================================
__global__ __launch_bounds__(256) void conv_tc_kernel(
    const float* __restrict__ x,     // [B][C][H][W]
    const float* __restrict__ cw,    // [Cout][Cin][3][3]
    const float* __restrict__ bias)  // [C]
{
    extern __shared__ unsigned char smem[];
    const uint32_t sb = smem_u32(smem);
    const int t = threadIdx.x;
    const int lane = t & 31;
    const int w = t >> 5;
    const int y0 = blockIdx.x * 2;
    const int b = blockIdx.y;
    const int orow = w >> 2;
    const int pxl = (w & 3) * 32;

    if (t < 64) *reinterpret_cast<float*>(smem + SM_BIAS + t * 4) = bias[t];

    for (int i = t; i < 4 * 2 * 9; i += 256) {
        int slab = i / 18;
        int rem = i - slab * 18;
        int row = (rem >= 9) ? 129 : 0;
        int q = (rem >= 9) ? rem - 9 : rem;
        *reinterpret_cast<uint4*>(smem + SM_A + slab * ATILE + row * ASTRIDE + q * 16) =
            make_uint4(0, 0, 0, 0);
    }

    for (int i = t; i < 1024; i += 256) {
        int oct = i & 7;
        int pxq = (i >> 3) & 31;
        int r = i >> 8;
        int yin = y0 - 1 + r;
        uint32_t sbase = sb + SM_A + r * ATILE + (pxq * 4 + 1) * ASTRIDE + oct * 16;
        if ((unsigned)yin < 128u) {
            float4 v0, v1, v2, v3, v4, v5, v6, v7;
            const float* xp = x + ((size_t)(b * CC + oct * 8) * HW + yin) * HW + pxq * 4;
            const size_t cs = (size_t)HW * HW;
            v0 = *reinterpret_cast<const float4*>(xp);
            v1 = *reinterpret_cast<const float4*>(xp + cs);
            v2 = *reinterpret_cast<const float4*>(xp + 2 * cs);
            v3 = *reinterpret_cast<const float4*>(xp + 3 * cs);
            v4 = *reinterpret_cast<const float4*>(xp + 4 * cs);
            v5 = *reinterpret_cast<const float4*>(xp + 5 * cs);
            v6 = *reinterpret_cast<const float4*>(xp + 6 * cs);
            v7 = *reinterpret_cast<const float4*>(xp + 7 * cs);
#define STORE_PX(cmp, pi) do { \
            uint4 ov; \
            ov.x = h2u(__floats2half2_rn(v0.cmp, v1.cmp)); \
            ov.y = h2u(__floats2half2_rn(v2.cmp, v3.cmp)); \
            ov.z = h2u(__floats2half2_rn(v4.cmp, v5.cmp)); \
            ov.w = h2u(__floats2half2_rn(v6.cmp, v7.cmp)); \
            asm volatile("st.shared.v4.b32 [%0], {%1,%2,%3,%4};" \
                :: "r"(sbase + (pi) * ASTRIDE), "r"(ov.x), "r"(ov.y), "r"(ov.z), "r"(ov.w)); \
        } while (0)
            STORE_PX(x, 0);
            STORE_PX(y, 1);
            STORE_PX(z, 2);
            STORE_PX(w, 3);
#undef STORE_PX
        } else {
#pragma unroll
            for (int pi = 0; pi < 4; ++pi)
                asm volatile("st.shared.v4.b32 [%0], {%1,%1,%1,%1};"
                             :: "r"(sbase + pi * ASTRIDE), "r"(0u));
        }
    }

    const uint32_t aLaneOff = (uint32_t)((lane & 15) * ASTRIDE + (lane >> 4) * 16);
    const uint32_t bLaneOff = (uint32_t)((((lane & 7) + ((lane >> 4) << 3)) * ASTRIDE) +
                                         ((lane >> 3) & 1) * 16);

    float acc[2][8][4];
#pragma unroll
    for (int mt = 0; mt < 2; ++mt)
#pragma unroll
        for (int nt = 0; nt < 8; ++nt)
#pragma unroll
            for (int q = 0; q < 4; ++q) acc[mt][nt][q] = 0.f;

    for (int dy = 0; dy < 3; ++dy) {
        __syncthreads();
        for (int i = t; i < 4096; i += 256) {
            int co = i >> 6, ci = i & 63;
            const float* wp = cw + co * 576 + ci * 9 + dy * 3;
            unsigned char* basep = smem + SM_B + co * ASTRIDE + ci * 2;
            *reinterpret_cast<__half*>(basep) = __float2half(wp[0]);
            *reinterpret_cast<__half*>(basep + BTILE) = __float2half(wp[1]);
            *reinterpret_cast<__half*>(basep + 2 * BTILE) = __float2half(wp[2]);
        }
        __syncthreads();

        const uint32_t sA = sb + SM_A + (uint32_t)(orow + dy) * ATILE;

#pragma unroll
        for (int ks = 0; ks < 4; ++ks) {
#pragma unroll
            for (int dx = 0; dx < 3; ++dx) {
                uint32_t bf[4][4];
                const uint32_t bBase = sb + SM_B + (uint32_t)dx * BTILE + ks * 32 + bLaneOff;
#pragma unroll
                for (int np = 0; np < 4; ++np)
                    ldsm4(bf[np], bBase + np * 16 * ASTRIDE);
                uint32_t af[2][4];
#pragma unroll
                for (int mt = 0; mt < 2; ++mt) {
                    const uint32_t arow = (uint32_t)(pxl + mt * 16 + dx);
                    ldsm4(af[mt], sA + arow * ASTRIDE + ks * 32 + aLaneOff);
                }
#pragma unroll
                for (int mt = 0; mt < 2; ++mt)
#pragma unroll
                    for (int np = 0; np < 4; ++np) {
                        mma16816h(acc[mt][2 * np],     af[mt], bf[np][0], bf[np][1]);
                        mma16816h(acc[mt][2 * np + 1], af[mt], bf[np][2], bf[np][3]);
                    }
            }
        }
    }

    const float* sbias = reinterpret_cast<const float*>(smem + SM_BIAS);
    const int y = y0 + orow;
    const int cq = (lane & 3) * 2;
    const int pxq = lane >> 2;
#pragma unroll
    for (int mt = 0; mt < 2; ++mt) {
#pragma unroll
        for (int half = 0; half < 2; ++half) {
            int px = pxl + mt * 16 + pxq + half * 8;
            float* dst = g_h + (((size_t)(b * HW) + y) * HW + px) * CC;
#pragma unroll
            for (int nt = 0; nt < 8; ++nt) {
                int co = nt * 8 + cq;
                float a0 = acc[mt][nt][half * 2 + 0] + sbias[co];
                float a1 = acc[mt][nt][half * 2 + 1] + sbias[co + 1];
                a0 = a0 > 0.f ? a0 : 0.02f * a0;
                a1 = a1 > 0.f ? a1 : 0.02f * a1;
                *reinterpret_cast<float2*>(dst + co) = make_float2(a0, a1);
            }
        }
    }
}

// ============================================================================
// Gather + FC v9: tensor-core GEMM per k. out[32b x 24o] = A[32 x 768] W^T.
// Block per k, 192 threads. A = gathered h rows (fp16, stride 1552B),
// B = pred_w fp16. 6 warps = (mt 2) x (nt 3) tiles, 48 k16 steps each,
// 2 interleaved accumulators to break the MMA RAW chain.
// ============================================================================
__global__ __launch_bounds__(192) void gather_mma_kernel(
    const int* __restrict__ pos,     // [K][B][L][2] (x, y)
    const float* __restrict__ pw,    // [24][768]
    const float* __restrict__ pb,    // [24]
    float* __restrict__ out)         // [K][B][24]
{
    extern __shared__ unsigned char gsm[];
    const uint32_t sb = smem_u32(gsm);
    const int t = threadIdx.x;
    const int lane = t & 31;
    const int w = t >> 5;
    const int k = blockIdx.x;

    // --- stage B: pred_w fp32 -> fp16 rows [24][776h] ---
    for (int i = t * 4; i < 24 * 768; i += 192 * 4) {
        int o = i / 768;
        int jl = i - o * 768;
        float4 v = *reinterpret_cast<const float4*>(&pw[o * 768 + jl]);
        uint32_t p0 = h2u(__floats2half2_rn(v.x, v.y));
        uint32_t p1 = h2u(__floats2half2_rn(v.z, v.w));
        asm volatile("st.shared.v2.b32 [%0], {%1,%2};"
                     :: "r"(sb + SM_GB + o * GSTRIDE_B + jl * 2), "r"(p0), "r"(p1));
    }

    // --- stage A: gather 384 (b,l) rows of 64 ch, fp32 -> fp16 ---
#pragma unroll
    for (int rep = 0; rep < 2; ++rep) {
        int it = t + rep * 192;
        int l = it >> 5;              // 0..11
        int b = it & 31;
        int2 pp = *reinterpret_cast<const int2*>(&pos[((k * BBATCH + b) * LL + l) * 2]);
        int px = pp.x < 0 ? 0 : (pp.x > 127 ? 127 : pp.x);
        int py = pp.y < 0 ? 0 : (pp.y > 127 ? 127 : pp.y);
        const float4* src = reinterpret_cast<const float4*>(
            &g_h[(((size_t)(b * HW) + py) * HW + px) * CC]);
        uint32_t dst = sb + SM_GA + b * GSTRIDE_B + l * 128;
#pragma unroll
        for (int q = 0; q < 8; ++q) {
            float4 f0 = src[2 * q];
            float4 f1 = src[2 * q + 1];
            uint32_t p0 = h2u(__floats2half2_rn(f0.x, f0.y));
            uint32_t p1 = h2u(__floats2half2_rn(f0.z, f0.w));
            uint32_t p2 = h2u(__floats2half2_rn(f1.x, f1.y));
            uint32_t p3 = h2u(__floats2half2_rn(f1.z, f1.w));
            asm volatile("st.shared.v4.b32 [%0], {%1,%2,%3,%4};"
                         :: "r"(dst + q * 16), "r"(p0), "r"(p1), "r"(p2), "r"(p3));
        }
    }
    __syncthreads();

    // --- mma phase: warp w < 6 handles tile (mt = w&1, nt = w>>1) ---
    if (w < 6) {
        const int mt = w & 1;
        const int nt = w >> 1;
        const uint32_t aBase = sb + SM_GA + (uint32_t)(mt * 16 + (lane & 15)) * GSTRIDE_B +
                               (lane >> 4) * 16;
        const uint32_t bBase = sb + SM_GB + (uint32_t)(nt * 8 + (lane & 7)) * GSTRIDE_B +
                               ((lane >> 3) & 1) * 16;

        float acc0[4] = {0.f, 0.f, 0.f, 0.f};
        float acc1[4] = {0.f, 0.f, 0.f, 0.f};
#pragma unroll
        for (int ks = 0; ks < 48; ks += 2) {
            uint32_t a0[4], a1[4], b0[2], b1[2];
            ldsm4(a0, aBase + ks * 32);
            ldsm2(b0, bBase + ks * 32);
            ldsm4(a1, aBase + ks * 32 + 32);
            ldsm2(b1, bBase + ks * 32 + 32);
            mma16816h(acc0, a0, b0[0], b0[1]);
            mma16816h(acc1, a1, b1[0], b1[1]);
        }

        const int b = mt * 16 + (lane >> 2);
        const int o = nt * 8 + (lane & 3) * 2;
        float2 bias2 = *reinterpret_cast<const float2*>(&pb[o]);
        float2 r0;
        r0.x = acc0[0] + acc1[0] + bias2.x;
        r0.y = acc0[1] + acc1[1] + bias2.y;
        *reinterpret_cast<float2*>(&out[((size_t)k * BBATCH + b) * OO + o]) = r0;
        float2 r1;
        r1.x = acc0[2] + acc1[2] + bias2.x;
        r1.y = acc0[3] + acc1[3] + bias2.y;
        *reinterpret_cast<float2*>(&out[((size_t)k * BBATCH + b + 8) * OO + o]) = r1;
    }
}

// ============================================================================
extern "C" void kernel_launch(void* const* d_in, const int* in_sizes, int n_in,
                              void* d_out, int out_size) {
    const float* x   = (const float*)d_in[0];   // [32][64][128][128]
    const int*   pos = (const int*)  d_in[1];   // [1000][32][12][2]
    const float* cw  = (const float*)d_in[2];   // [64][64][3][3]
    const float* cb  = (const float*)d_in[3];   // [64]
    const float* pw  = (const float*)d_in[4];   // [24][768]
    const float* pb  = (const float*)d_in[5];   // [24]
    float* out = (float*)d_out;                 // [1000][32][24]

    cudaFuncSetAttribute(conv_tc_kernel, cudaFuncAttributeMaxDynamicSharedMemorySize, SM_TOT);
    cudaFuncSetAttribute(gather_mma_kernel, cudaFuncAttributeMaxDynamicSharedMemorySize, G_TOT);

    conv_tc_kernel<<<dim3(HW / 2, BBATCH), 256, SM_TOT>>>(x, cw, cb);
    gather_mma_kernel<<<KK, 192, G_TOT>>>(pos, pw, pb, out);
}